// round 6
// baseline (speedup 1.0000x reference)
#include <cuda_runtime.h>
#include <cooperative_groups.h>

namespace cg = cooperative_groups;

// Problem constants (fixed shapes)
#define NN    5000      // graph nodes
#define MM    10        // template nodes
#define NT    16        // templates
#define FF    128       // features
#define NFW   3         // Frank-Wolfe iters
#define NSINK 10        // Sinkhorn iters
#define NC    8         // CTAs per cluster (per template)
#define RPC   (NN/NC)   // rows per CTA = 625
#define TPB   512
#define NWARP (TPB/32)
#define WS    160       // bitmap words per row (157 used, padded)
#define EMAX  80000

// ---------------- device scratch (static; no allocation) ----------------
__device__ unsigned int g_bitmap[NN * WS];       // 3.2 MB
__device__ int   g_deg[NN];
__device__ int   g_rowptr[NN + 1];
__device__ int   g_cols[EMAX];
__device__ float g_Y[(size_t)NT * NN * MM];      // 3.2 MB: dT@C2 per template

// ---------------- preprocessing kernels ----------------
__global__ void k_clear() {
    int i = blockIdx.x * blockDim.x + threadIdx.x;
    if (i < NN * WS) g_bitmap[i] = 0u;
}

__global__ void k_mark(const int* __restrict__ ei, int E) {
    int e = blockIdx.x * blockDim.x + threadIdx.x;
    if (e >= E) return;
    int s = ei[e];
    int d = ei[E + e];
    atomicOr(&g_bitmap[s * WS + (d >> 5)], 1u << (d & 31));
}

// one warp per row: deduped degree via popcount
__global__ void k_deg() {
    int w    = (blockIdx.x * blockDim.x + threadIdx.x) >> 5;
    int lane = threadIdx.x & 31;
    if (w >= NN) return;
    const unsigned int* bp = g_bitmap + (size_t)w * WS;
    int c = 0;
    #pragma unroll
    for (int k = 0; k < 5; k++) c += __popc(bp[lane * 5 + k]);  // 32*5 = 160 words
    #pragma unroll
    for (int o = 16; o; o >>= 1) c += __shfl_xor_sync(0xffffffffu, c, o);
    if (lane == 0) g_deg[w] = c;
}

// single-block exclusive scan of g_deg -> g_rowptr
__global__ void k_scan() {
    __shared__ int ss[1024];
    int tid = threadIdx.x;
    int base = tid * 5;
    int loc[5];
    int s = 0;
    #pragma unroll
    for (int k = 0; k < 5; k++) {
        int v = (base + k < NN) ? g_deg[base + k] : 0;
        loc[k] = v; s += v;
    }
    ss[tid] = s;
    __syncthreads();
    for (int off = 1; off < 1024; off <<= 1) {
        int v = (tid >= off) ? ss[tid - off] : 0;
        __syncthreads();
        ss[tid] += v;
        __syncthreads();
    }
    int excl = ss[tid] - s;
    #pragma unroll
    for (int k = 0; k < 5; k++) {
        if (base + k < NN) { g_rowptr[base + k] = excl; excl += loc[k]; }
    }
    if (tid == 1023) g_rowptr[NN] = ss[1023];
}

// one warp per row: emit sorted column indices (deterministic CSR)
__global__ void k_fill() {
    int w    = (blockIdx.x * blockDim.x + threadIdx.x) >> 5;
    int lane = threadIdx.x & 31;
    if (w >= NN) return;
    const unsigned int* bp = g_bitmap + (size_t)w * WS;
    unsigned int wd[5];
    int c = 0;
    #pragma unroll
    for (int k = 0; k < 5; k++) { wd[k] = bp[lane * 5 + k]; c += __popc(wd[k]); }
    int inc = c;
    #pragma unroll
    for (int o = 1; o < 32; o <<= 1) {
        int v = __shfl_up_sync(0xffffffffu, inc, o);
        if (lane >= o) inc += v;
    }
    int pos = g_rowptr[w] + inc - c;
    #pragma unroll
    for (int k = 0; k < 5; k++) {
        unsigned int x = wd[k];
        int bb = (lane * 5 + k) * 32;
        while (x) {
            int b = __ffs(x) - 1;
            g_cols[pos++] = bb + b;
            x &= x - 1;
        }
    }
}

// ---------------- main FGW kernel: one 8-CTA cluster per template ----------------
struct __align__(16) Smem {
    float M[RPC * MM];
    float K[RPC * MM];      // holds G, then K = exp(-(G-c)/reg)
    float T[RPC * MM];
    float ATC[RPC * MM];
    float AdT[RPC * MM];
    float DegN[RPC];        // deg_i / N  ( = ((A*A)@p)_i )
    float U[RPC];
    float F2[MM * FF];
    float C2[MM * MM];
    float q[MM], qC2[MM], cc[MM], fsq[MM];
    float V[MM];
    float Pub[2][16];       // double-buffered cluster exchange
    float Wred[NWARP][MM];  // block-reduction scratch
    float Scal[4];          // [0]=reg [1]=cmin [2]=gamma
};

__global__ void __launch_bounds__(TPB, 1) __cluster_dims__(NC, 1, 1)
k_main(const float* __restrict__ x,
       const float* __restrict__ tA,
       const float* __restrict__ tF,
       const float* __restrict__ q0,
       const float* __restrict__ a0,
       float* __restrict__ out)
{
    extern __shared__ char smem_raw[];
    Smem* s = reinterpret_cast<Smem*>(smem_raw);
    cg::cluster_group cluster = cg::this_cluster();
    const int rank = (int)cluster.block_rank();
    const int tpl  = blockIdx.x / NC;
    const int tid  = threadIdx.x;
    const int wid  = tid >> 5, lane = tid & 31;
    const int r0   = rank * RPC;
    const float P  = 1.0f / (float)NN;
    const float alpha = 1.0f / (1.0f + expf(-a0[0]));
    const float oma = 1.0f - alpha, ta = 2.0f * alpha;
    int par = 0;

    // ---- phase 0: per-template small data ----
    for (int i = tid; i < MM * FF; i += TPB) s->F2[i] = tF[(size_t)tpl * MM * FF + i];
    if (tid < MM * MM) s->C2[tid] = tA[tpl * MM * MM + tid];
    if (tid == 0) {
        float qq[MM]; float mx = -1e30f;
        #pragma unroll
        for (int k = 0; k < MM; k++) { qq[k] = q0[tpl * MM + k]; mx = fmaxf(mx, qq[k]); }
        float ssum = 0.f;
        #pragma unroll
        for (int k = 0; k < MM; k++) { qq[k] = expf(qq[k] - mx); ssum += qq[k]; }
        #pragma unroll
        for (int k = 0; k < MM; k++) s->q[k] = qq[k] / ssum;
    }
    __syncthreads();
    if (tid < MM) {
        int j = tid;
        float a1 = 0.f, a2 = 0.f, a3 = 0.f;
        #pragma unroll
        for (int k = 0; k < MM; k++) {
            a1 += s->q[k] * s->C2[k * MM + j];
            float cj = s->C2[j * MM + k];
            a2 += cj * cj * s->q[k];
        }
        for (int c = 0; c < FF; c++) { float fv = s->F2[j * FF + c]; a3 += fv * fv; }
        s->qC2[j] = a1; s->cc[j] = a2; s->fsq[j] = a3;
    }
    __syncthreads();

    // ---- phase 1: M (feature cost), DegN, T0 = p q^T, ATC0 (closed form) ----
    for (int r = wid; r < RPC; r += NWARP) {
        int gi = r0 + r;
        const float* xr = x + (size_t)gi * FF;
        float acc[MM];
        #pragma unroll
        for (int j = 0; j < MM; j++) acc[j] = 0.f;
        float xs = 0.f;
        #pragma unroll
        for (int c = 0; c < FF / 32; c++) {
            float xv = xr[c * 32 + lane];
            xs += xv * xv;
            #pragma unroll
            for (int j = 0; j < MM; j++) acc[j] += xv * s->F2[j * FF + c * 32 + lane];
        }
        #pragma unroll
        for (int o = 16; o; o >>= 1) {
            xs += __shfl_xor_sync(0xffffffffu, xs, o);
            #pragma unroll
            for (int j = 0; j < MM; j++) acc[j] += __shfl_xor_sync(0xffffffffu, acc[j], o);
        }
        float dn = (float)g_deg[gi] * P;
        if (lane == 0) s->DegN[r] = dn;
        if (lane < MM) {
            int j = lane;
            s->M[r * MM + j]   = xs + s->fsq[j] - 2.f * acc[j];
            s->T[r * MM + j]   = P * s->q[j];
            s->ATC[r * MM + j] = dn * s->qC2[j];
        }
    }
    __syncthreads();

    // ---- Frank-Wolfe loop ----
    for (int fw = 0; fw < NFW; fw++) {
        // (a) G = (1-a)M + 2a(constC - 2 ATC); stats: sum|G|, min G
        float psum = 0.f, pmin = 1e30f;
        for (int li = tid; li < RPC; li += TPB) {
            float dn = s->DegN[li];
            #pragma unroll
            for (int j = 0; j < MM; j++) {
                int e = li * MM + j;
                float g = oma * s->M[e] + ta * (dn + s->cc[j] - 2.f * s->ATC[e]);
                s->K[e] = g;
                psum += fabsf(g);
                pmin = fminf(pmin, g);
            }
        }
        #pragma unroll
        for (int o = 16; o; o >>= 1) {
            psum += __shfl_xor_sync(0xffffffffu, psum, o);
            pmin = fminf(pmin, __shfl_xor_sync(0xffffffffu, pmin, o));
        }
        if (lane == 0) { s->Wred[wid][0] = psum; s->Wred[wid][1] = pmin; }
        __syncthreads();
        if (tid == 0) {
            float bs = 0.f, bm = 1e30f;
            for (int w = 0; w < NWARP; w++) { bs += s->Wred[w][0]; bm = fminf(bm, s->Wred[w][1]); }
            s->Pub[par][0] = bs; s->Pub[par][1] = bm;
        }
        cluster.sync();
        if (tid == 0) {
            float bs = 0.f, bm = 1e30f;
            for (int r = 0; r < NC; r++) {
                const float* rp = cluster.map_shared_rank(&s->Pub[0][0], r);
                bs += rp[par * 16 + 0];
                bm = fminf(bm, rp[par * 16 + 1]);
            }
            s->Scal[0] = 0.05f * (bs / (float)(NN * MM)) + 1e-9f;  // reg
            s->Scal[1] = bm;                                        // cmin
        }
        if (tid < MM) s->V[tid] = 1.f;   // reset Sinkhorn scaling (g=0)
        par ^= 1;
        __syncthreads();

        // (b) K = exp(-(G - cmin)/reg)  (exact shift invariance)
        {
            float reg = s->Scal[0], cmin = s->Scal[1];
            float inv = 1.0f / reg;
            for (int li = tid; li < RPC; li += TPB) {
                #pragma unroll
                for (int j = 0; j < MM; j++) {
                    int e = li * MM + j;
                    s->K[e] = expf(fmaxf((cmin - s->K[e]) * inv, -80.f));
                }
            }
        }

        // (c) Sinkhorn: u = p/(Kv); v = q/(K^T u); one cluster.sync per iter
        for (int it = 0; it < NSINK; it++) {
            float vr[MM];
            #pragma unroll
            for (int j = 0; j < MM; j++) vr[j] = s->V[j];
            float col[MM];
            #pragma unroll
            for (int j = 0; j < MM; j++) col[j] = 0.f;
            for (int li = tid; li < RPC; li += TPB) {
                float kr[MM];
                #pragma unroll
                for (int j = 0; j < MM; j++) kr[j] = s->K[li * MM + j];
                float kv = 0.f;
                #pragma unroll
                for (int j = 0; j < MM; j++) kv += kr[j] * vr[j];
                float u = P / kv;
                s->U[li] = u;
                #pragma unroll
                for (int j = 0; j < MM; j++) col[j] += kr[j] * u;
            }
            #pragma unroll
            for (int o = 16; o; o >>= 1) {
                #pragma unroll
                for (int j = 0; j < MM; j++) col[j] += __shfl_xor_sync(0xffffffffu, col[j], o);
            }
            if (lane == 0) {
                #pragma unroll
                for (int j = 0; j < MM; j++) s->Wred[wid][j] = col[j];
            }
            __syncthreads();
            if (tid < MM) {
                float t = 0.f;
                for (int w = 0; w < NWARP; w++) t += s->Wred[w][tid];
                s->Pub[par][tid] = t;
            }
            cluster.sync();
            if (tid < MM) {
                float tot = 0.f;
                for (int r = 0; r < NC; r++) {
                    const float* rp = cluster.map_shared_rank(&s->Pub[0][0], r);
                    tot += rp[par * 16 + tid];
                }
                s->V[tid] = s->q[tid] / tot;
            }
            par ^= 1;
            __syncthreads();
        }

        // (d) dT = u.K.v - T; Y = dT@C2 -> global; partial dots for b
        float pM = 0.f, pC = 0.f, pA = 0.f;
        {
            float vr[MM];
            #pragma unroll
            for (int j = 0; j < MM; j++) vr[j] = s->V[j];
            for (int li = tid; li < RPC; li += TPB) {
                float u = s->U[li];
                float d[MM];
                #pragma unroll
                for (int j = 0; j < MM; j++) {
                    int e = li * MM + j;
                    d[j] = u * s->K[e] * vr[j] - s->T[e];
                }
                float dn = s->DegN[li];
                #pragma unroll
                for (int j = 0; j < MM; j++) {
                    int e = li * MM + j;
                    pM += s->M[e] * d[j];
                    pC += (dn + s->cc[j]) * d[j];
                    pA += s->ATC[e] * d[j];
                }
                float* yp = g_Y + ((size_t)tpl * NN + (r0 + li)) * MM;
                #pragma unroll
                for (int jj = 0; jj < MM; jj++) {
                    float y = 0.f;
                    #pragma unroll
                    for (int j = 0; j < MM; j++) y += d[j] * s->C2[j * MM + jj];
                    yp[jj] = y;
                }
            }
        }
        __threadfence();
        cluster.sync();

        // (e) SpMM: AdTC = A @ Y (CSR, deduped, sorted -> deterministic); pa
        float pa = 0.f;
        {
            float vr[MM];
            #pragma unroll
            for (int j = 0; j < MM; j++) vr[j] = s->V[j];
            for (int li = tid; li < RPC; li += TPB) {
                int gi = r0 + li;
                int b = g_rowptr[gi], en = g_rowptr[gi + 1];
                float acc[MM];
                #pragma unroll
                for (int j = 0; j < MM; j++) acc[j] = 0.f;
                for (int p2 = b; p2 < en; p2++) {
                    int col = g_cols[p2];
                    const float2* yp = reinterpret_cast<const float2*>(
                        g_Y + ((size_t)tpl * NN + col) * MM);
                    float2 v0 = __ldg(yp + 0), v1 = __ldg(yp + 1), v2 = __ldg(yp + 2),
                           v3 = __ldg(yp + 3), v4 = __ldg(yp + 4);
                    acc[0] += v0.x; acc[1] += v0.y;
                    acc[2] += v1.x; acc[3] += v1.y;
                    acc[4] += v2.x; acc[5] += v2.y;
                    acc[6] += v3.x; acc[7] += v3.y;
                    acc[8] += v4.x; acc[9] += v4.y;
                }
                float u = s->U[li];
                #pragma unroll
                for (int j = 0; j < MM; j++) {
                    int e = li * MM + j;
                    s->AdT[e] = acc[j];
                    float d = u * s->K[e] * vr[j] - s->T[e];
                    pa += acc[j] * d;
                }
            }
        }

        // (f) reduce (pa, pM, pC, pA) block+cluster; compute gamma
        #pragma unroll
        for (int o = 16; o; o >>= 1) {
            pa += __shfl_xor_sync(0xffffffffu, pa, o);
            pM += __shfl_xor_sync(0xffffffffu, pM, o);
            pC += __shfl_xor_sync(0xffffffffu, pC, o);
            pA += __shfl_xor_sync(0xffffffffu, pA, o);
        }
        if (lane == 0) {
            s->Wred[wid][0] = pa; s->Wred[wid][1] = pM;
            s->Wred[wid][2] = pC; s->Wred[wid][3] = pA;
        }
        __syncthreads();
        if (tid == 0) {
            float t0 = 0, t1 = 0, t2 = 0, t3 = 0;
            for (int w = 0; w < NWARP; w++) {
                t0 += s->Wred[w][0]; t1 += s->Wred[w][1];
                t2 += s->Wred[w][2]; t3 += s->Wred[w][3];
            }
            s->Pub[par][0] = t0; s->Pub[par][1] = t1;
            s->Pub[par][2] = t2; s->Pub[par][3] = t3;
        }
        cluster.sync();
        if (tid == 0) {
            float Ta = 0, Tm = 0, Tc = 0, TA = 0;
            for (int r = 0; r < NC; r++) {
                const float* rp = cluster.map_shared_rank(&s->Pub[0][0], r);
                Ta += rp[par * 16 + 0]; Tm += rp[par * 16 + 1];
                Tc += rp[par * 16 + 2]; TA += rp[par * 16 + 3];
            }
            float a = -2.f * alpha * Ta;
            float b = oma * Tm + alpha * (Tc - 4.f * TA);
            float gam;
            if (a > 0.f) {
                gam = -b / (2.f * a + 1e-16f);
                gam = fminf(fmaxf(gam, 0.f), 1.f);
            } else {
                gam = (a + b < 0.f) ? 1.f : 0.f;
            }
            s->Scal[2] = gam;
        }
        par ^= 1;
        __syncthreads();

        // (g) T += gam*dT; ATC += gam*AdTC
        {
            float gam = s->Scal[2];
            float vr[MM];
            #pragma unroll
            for (int j = 0; j < MM; j++) vr[j] = s->V[j];
            for (int li = tid; li < RPC; li += TPB) {
                float u = s->U[li];
                #pragma unroll
                for (int j = 0; j < MM; j++) {
                    int e = li * MM + j;
                    float d = u * s->K[e] * vr[j] - s->T[e];
                    s->T[e]   += gam * d;
                    s->ATC[e] += gam * s->AdT[e];
                }
            }
        }
        __syncthreads();
    }

    // ---- final FGW distance ----
    float pd = 0.f;
    for (int li = tid; li < RPC; li += TPB) {
        float dn = s->DegN[li];
        #pragma unroll
        for (int j = 0; j < MM; j++) {
            int e = li * MM + j;
            float t = s->T[e];
            pd += oma * s->M[e] * t + alpha * ((dn + s->cc[j]) * t - 2.f * s->ATC[e] * t);
        }
    }
    #pragma unroll
    for (int o = 16; o; o >>= 1) pd += __shfl_xor_sync(0xffffffffu, pd, o);
    if (lane == 0) s->Wred[wid][0] = pd;
    __syncthreads();
    if (tid == 0) {
        float bs = 0.f;
        for (int w = 0; w < NWARP; w++) bs += s->Wred[w][0];
        s->Pub[par][0] = bs;
    }
    cluster.sync();
    if (rank == 0 && tid == 0) {
        float tot = 0.f;
        for (int r = 0; r < NC; r++) {
            const float* rp = cluster.map_shared_rank(&s->Pub[0][0], r);
            tot += rp[par * 16 + 0];
        }
        out[tpl] = tot;
    }
    cluster.sync();  // keep all CTAs alive until DSMEM reads complete
}

// ---------------- launch ----------------
extern "C" void kernel_launch(void* const* d_in, const int* in_sizes, int n_in,
                              void* d_out, int out_size)
{
    const float* x  = (const float*)d_in[0];
    const int*   ei = (const int*)  d_in[1];
    const float* tA = (const float*)d_in[2];
    const float* tF = (const float*)d_in[3];
    const float* q0 = (const float*)d_in[4];
    const float* a0 = (const float*)d_in[5];
    float* out = (float*)d_out;
    int E = in_sizes[1] / 2;

    cudaFuncSetAttribute(k_main, cudaFuncAttributeMaxDynamicSharedMemorySize,
                         (int)sizeof(Smem));

    k_clear<<<(NN * WS + 255) / 256, 256>>>();
    k_mark<<<(E + 255) / 256, 256>>>(ei, E);
    k_deg<<<(NN * 32 + 255) / 256, 256>>>();
    k_scan<<<1, 1024>>>();
    k_fill<<<(NN * 32 + 255) / 256, 256>>>();
    k_main<<<NT * NC, TPB, sizeof(Smem)>>>(x, tA, tF, q0, a0, out);
}